// round 11
// baseline (speedup 1.0000x reference)
#include <cuda_runtime.h>
#include <cstdint>

// YOLO layer: x (64, 255, 44, 44) f32 -> out (64, 5808, 85) f32.
//   out[b, a*1936 + s, c] = f(x[b, a*85 + c, s])
//   c==0:(sig+gx)*8  c==1:(sig+gy)*8  c==2:exp*aw  c==3:exp*ah  c>=4:sig
//
// R11 = R6 read body (proven best) + R7 pipelining, at FULL 48 warps/SM:
// persistent 456 CTAs (3/SM), each 8 tiles, double-buffered smem
// (2 x 35,360B, TS=104; 3 x 70.7KB = 212KB/SM fits). TMA bulk write of
// tile i overlaps the LDG read phase of tile i+1 (wait_group.read 1 gates
// buffer reuse); per-tile TMA drain stall of R6 is gone.
// Read: warp-per-channel LDG.128 (lanes 0..25), STS stride-85 smem.
// Write: ONE cp.async.bulk per tile, contiguous.
// Sigmoid: 4-instruction approx (FMUL, MUFU.EX2, FADD, MUFU.RCP).

#define G44    44
#define GG     1936
#define CH     85
#define NA     3
#define TS     104
#define NTHR   512
#define NWARP  16
#define TPB    19                  // ceil(1936/104): 18 full + tail of 64
#define NTILES (192 * TPB)         // 3648
#define NCTA   456                 // 3 per SM x 152 SMs; 3648/456 = 8 each
#define TILE_F (TS * CH)           // 8840 floats = 35,360 B per buffer

__constant__ float c_aw[NA] = {10.0f, 16.0f, 33.0f};   // scaled_anchor*STRIDE
__constant__ float c_ah[NA] = {13.0f, 30.0f, 23.0f};

__device__ __forceinline__ float sig_(float v) {
    float e;
    asm("ex2.approx.ftz.f32 %0, %1;" : "=f"(e) : "f"(v * -1.442695041f));
    float r;
    asm("rcp.approx.ftz.f32 %0, %1;" : "=f"(r) : "f"(1.0f + e));
    return r;
}

__device__ __forceinline__ float exp_(float v) {
    float e;
    asm("ex2.approx.ftz.f32 %0, %1;" : "=f"(e) : "f"(v * 1.442695041f));
    return e;
}

extern __shared__ float smbuf[];   // 2 * TILE_F floats = 70,720 B

__global__ __launch_bounds__(NTHR, 3)
void yolo_kernel(const float* __restrict__ x, float* __restrict__ out) {
    const int warp = threadIdx.x >> 5;
    const int lane = threadIdx.x & 31;
    const int sl   = lane << 2;                 // 0..124; active if < valid

    int it = 0;
    for (int t = blockIdx.x; t < NTILES; t += NCTA, ++it) {
        float* sm = smbuf + (it & 1) * TILE_F;

        const int ba = t / TPB;                 // b*NA + a
        const int a  = ba % NA;
        const int s0 = (t - ba * TPB) * TS;
        const int valid = min(TS, GG - s0);     // 104, or 64 on last s-tile

        // gate: bulk write issued 2 iterations ago (same buffer) must be done
        if (threadIdx.x == 0)
            asm volatile("cp.async.bulk.wait_group.read 1;" ::: "memory");
        __syncthreads();

        if (sl < valid) {                       // lanes 26..31 idle
            const float* __restrict__ ib =
                x + (size_t)ba * (CH * GG) + (s0 + sl);
            float* __restrict__ row = sm + sl * CH;

            // ---- k = 0: channels 0..15 (special cases, warp-uniform) ----
            {
                const int ch = warp;
                const float4 v = *(const float4*)(ib + (size_t)ch * GG);
                float t0, t1, t2, t3;
                if (ch >= 4) {
                    t0 = sig_(v.x); t1 = sig_(v.y);
                    t2 = sig_(v.z); t3 = sig_(v.w);
                } else if (ch == 0) {
                    const int s  = s0 + sl;                 // s % 4 == 0
                    const int gx = s - (s / G44) * G44;     // gx+3 <= 43
                    t0 = (sig_(v.x) + (float)(gx + 0)) * 8.0f;
                    t1 = (sig_(v.y) + (float)(gx + 1)) * 8.0f;
                    t2 = (sig_(v.z) + (float)(gx + 2)) * 8.0f;
                    t3 = (sig_(v.w) + (float)(gx + 3)) * 8.0f;
                } else if (ch == 1) {
                    const float fy = (float)((s0 + sl) / G44);
                    t0 = (sig_(v.x) + fy) * 8.0f;
                    t1 = (sig_(v.y) + fy) * 8.0f;
                    t2 = (sig_(v.z) + fy) * 8.0f;
                    t3 = (sig_(v.w) + fy) * 8.0f;
                } else if (ch == 2) {
                    const float aw = c_aw[a];
                    t0 = exp_(v.x) * aw; t1 = exp_(v.y) * aw;
                    t2 = exp_(v.z) * aw; t3 = exp_(v.w) * aw;
                } else {                                    // ch == 3
                    const float ah = c_ah[a];
                    t0 = exp_(v.x) * ah; t1 = exp_(v.y) * ah;
                    t2 = exp_(v.z) * ah; t3 = exp_(v.w) * ah;
                }
                row[0 * CH + ch] = t0;
                row[1 * CH + ch] = t1;
                row[2 * CH + ch] = t2;
                row[3 * CH + ch] = t3;
            }

            // ---- k = 1..5: pure sigmoid ----
            #pragma unroll
            for (int k = 1; k < 6; k++) {
                const int ch = warp + k * NWARP;            // 16..95
                if (ch < CH) {                              // warp-uniform
                    const float4 v = *(const float4*)(ib + (size_t)ch * GG);
                    row[0 * CH + ch] = sig_(v.x);
                    row[1 * CH + ch] = sig_(v.y);
                    row[2 * CH + ch] = sig_(v.z);
                    row[3 * CH + ch] = sig_(v.w);
                }
            }
        }

        __syncthreads();

        // ---- commit bulk write, NO wait (overlaps next tile's reads) ----
        if (threadIdx.x == 0) {
            uint32_t saddr;
            asm volatile("{ .reg .u64 t; cvta.to.shared.u64 t, %1; cvt.u32.u64 %0, t; }"
                         : "=r"(saddr) : "l"(sm));
            float* gptr = out + ((size_t)ba * GG + s0) * CH;   // 416*bx bytes: 16B-aligned
            const uint32_t bytes = (uint32_t)(valid * CH * 4); // multiple of 16

            asm volatile("fence.proxy.async.shared::cta;" ::: "memory");
            asm volatile("cp.async.bulk.global.shared::cta.bulk_group [%0], [%1], %2;"
                         :: "l"(gptr), "r"(saddr), "r"(bytes) : "memory");
            asm volatile("cp.async.bulk.commit_group;" ::: "memory");
        }
    }

    // drain before exit (smem must stay alive for pending TMA reads)
    if (threadIdx.x == 0)
        asm volatile("cp.async.bulk.wait_group.read 0;" ::: "memory");
}

extern "C" void kernel_launch(void* const* d_in, const int* in_sizes, int n_in,
                              void* d_out, int out_size) {
    const float* x = (const float*)d_in[0];
    float* out = (float*)d_out;

    static const size_t shmem = 2 * TILE_F * sizeof(float);   // 70,720 B
    static bool configured = false;
    if (!configured) {
        cudaFuncSetAttribute(yolo_kernel,
                             cudaFuncAttributeMaxDynamicSharedMemorySize,
                             (int)shmem);
        configured = true;
    }

    yolo_kernel<<<NCTA, NTHR, shmem>>>(x, out);
}

// round 12
// speedup vs baseline: 1.0602x; 1.0602x over previous
#include <cuda_runtime.h>
#include <cstdint>

// YOLO layer: x (64, 255, 44, 44) f32 -> out (64, 5808, 85) f32.
//   out[b, a*1936 + s, c] = f(x[b, a*85 + c, s])
//   c==0:(sig+gx)*8  c==1:(sig+gy)*8  c==2:exp*aw  c==3:exp*ah  c>=4:sig
//
// R12 = R6 body (champion, 37.06us ncu, DRAM 68%) at 1024-thread CTAs:
// 2 CTAs x 1024 thr = 2048 thr = 64 warps/SM (vs ~50 before — every 512-thr
// config was capped at 3 CTAs by the ~164KB smem tier; 2 x 43.5KB = 87KB
// sidesteps it entirely). 32 warps/CTA, each owns ~3 channels:
//   k=0: ch=w      (0..31, specials w<4, warp-uniform)
//   k=1: ch=w+32   (32..63)
//   k=2: ch=w+64   (64..84, w<21)
// Read: warp-per-channel LDG.128 along s, STS.32 x4 into output-layout smem.
// Write: ONE cp.async.bulk (shared->global) per tile, contiguous 43,520 B.
// Sigmoid: 4-instruction approx (FMUL, MUFU.EX2, FADD, MUFU.RCP).

#define G44   44
#define GG    1936
#define CH    85
#define NA    3
#define TS    128
#define NTHR  1024

__constant__ float c_aw[NA] = {10.0f, 16.0f, 33.0f};   // scaled_anchor*STRIDE
__constant__ float c_ah[NA] = {13.0f, 30.0f, 23.0f};

__device__ __forceinline__ float sig_(float v) {
    float e;
    asm("ex2.approx.ftz.f32 %0, %1;" : "=f"(e) : "f"(v * -1.442695041f));
    float r;
    asm("rcp.approx.ftz.f32 %0, %1;" : "=f"(r) : "f"(1.0f + e));
    return r;
}

__device__ __forceinline__ float exp_(float v) {
    float e;
    asm("ex2.approx.ftz.f32 %0, %1;" : "=f"(e) : "f"(v * 1.442695041f));
    return e;
}

__global__ __launch_bounds__(NTHR, 2)
void yolo_kernel(const float* __restrict__ x, float* __restrict__ out) {
    __shared__ __align__(16) float sm[TS * CH];   // 43,520 B, output layout

    const int ba   = blockIdx.y;                  // b*NA + a (0..191)
    const int a    = ba % NA;
    const int s0   = blockIdx.x * TS;
    const int warp = threadIdx.x >> 5;            // 0..31
    const int lane = threadIdx.x & 31;
    const int valid = min(TS, GG - s0);           // 128, or 16 on last tile

    const int sl = lane << 2;                     // spatial offset within tile
    if (sl < valid) {
        const float* __restrict__ ib = x + (size_t)ba * (CH * GG) + (s0 + sl);
        float* __restrict__ row = sm + sl * CH;   // stride-85 STS: conflict-free

        // ---- k = 0: ch = warp (0..31); specials live only here ----
        {
            const int ch = warp;
            const float4 v = *(const float4*)(ib + (size_t)ch * GG);
            float t0, t1, t2, t3;
            if (ch >= 4) {                        // warp-uniform
                t0 = sig_(v.x); t1 = sig_(v.y); t2 = sig_(v.z); t3 = sig_(v.w);
            } else if (ch == 0) {
                const int s  = s0 + sl;
                const int gx = s - (s / G44) * G44;   // s%4==0, 44%4==0
                t0 = (sig_(v.x) + (float)(gx + 0)) * 8.0f;
                t1 = (sig_(v.y) + (float)(gx + 1)) * 8.0f;
                t2 = (sig_(v.z) + (float)(gx + 2)) * 8.0f;
                t3 = (sig_(v.w) + (float)(gx + 3)) * 8.0f;
            } else if (ch == 1) {
                const float fy = (float)((s0 + sl) / G44);
                t0 = (sig_(v.x) + fy) * 8.0f;
                t1 = (sig_(v.y) + fy) * 8.0f;
                t2 = (sig_(v.z) + fy) * 8.0f;
                t3 = (sig_(v.w) + fy) * 8.0f;
            } else if (ch == 2) {
                const float aw = c_aw[a];
                t0 = exp_(v.x) * aw; t1 = exp_(v.y) * aw;
                t2 = exp_(v.z) * aw; t3 = exp_(v.w) * aw;
            } else {                              // ch == 3
                const float ah = c_ah[a];
                t0 = exp_(v.x) * ah; t1 = exp_(v.y) * ah;
                t2 = exp_(v.z) * ah; t3 = exp_(v.w) * ah;
            }
            row[0 * CH + ch] = t0;
            row[1 * CH + ch] = t1;
            row[2 * CH + ch] = t2;
            row[3 * CH + ch] = t3;
        }

        // ---- k = 1: ch = warp + 32 (32..63), pure sigmoid ----
        {
            const int ch = warp + 32;
            const float4 v = *(const float4*)(ib + (size_t)ch * GG);
            row[0 * CH + ch] = sig_(v.x);
            row[1 * CH + ch] = sig_(v.y);
            row[2 * CH + ch] = sig_(v.z);
            row[3 * CH + ch] = sig_(v.w);
        }

        // ---- k = 2: ch = warp + 64 (64..84), warps 0..20 only ----
        if (warp < 21) {
            const int ch = warp + 64;
            const float4 v = *(const float4*)(ib + (size_t)ch * GG);
            row[0 * CH + ch] = sig_(v.x);
            row[1 * CH + ch] = sig_(v.y);
            row[2 * CH + ch] = sig_(v.z);
            row[3 * CH + ch] = sig_(v.w);
        }
    }

    __syncthreads();

    // ---- write: single bulk async copy smem -> gmem (contiguous tile) ----
    if (threadIdx.x == 0) {
        uint32_t saddr;
        asm volatile("{ .reg .u64 t; cvta.to.shared.u64 t, %1; cvt.u32.u64 %0, t; }"
                     : "=r"(saddr) : "l"(sm));
        float* gptr = out + ((size_t)ba * GG + s0) * CH;   // 16B-aligned
        const uint32_t bytes = (uint32_t)(valid * CH * 4); // multiple of 16

        asm volatile("fence.proxy.async.shared::cta;" ::: "memory");
        asm volatile("cp.async.bulk.global.shared::cta.bulk_group [%0], [%1], %2;"
                     :: "l"(gptr), "r"(saddr), "r"(bytes) : "memory");
        asm volatile("cp.async.bulk.commit_group;" ::: "memory");
        asm volatile("cp.async.bulk.wait_group.read 0;" ::: "memory");
    }
}

extern "C" void kernel_launch(void* const* d_in, const int* in_sizes, int n_in,
                              void* d_out, int out_size) {
    const float* x = (const float*)d_in[0];
    float* out = (float*)d_out;

    dim3 grid((GG + TS - 1) / TS,   // 16 spatial tiles
              64 * NA);             // 192 (b,a) matrices
    yolo_kernel<<<grid, NTHR>>>(x, out);
}

// round 13
// speedup vs baseline: 1.3205x; 1.2455x over previous
#include <cuda_runtime.h>
#include <cstdint>

// YOLO layer: x (64, 255, 44, 44) f32 -> out (64, 5808, 85) f32.
//   out[b, a*1936 + s, c] = f(x[b, a*85 + c, s])
//   c==0:(sig+gx)*8  c==1:(sig+gy)*8  c==2:exp*aw  c==3:exp*ah  c>=4:sig
//
// R13 = R6 champion body + FRONT-BATCHED loads, nothing else changed.
// Evidence: sm_103a caps 1536 thr/SM (every 4x512 / 2x1024 attempt failed),
// so 48 warps is max; DRAM% tracked per-warp load concurrency across rounds
// (R6 ~2 in flight -> 68%, R12 ~1 -> 56%). Issue all 6 independent LDG.128
// before any transform -> MLP=6/thread. R8's front-batch regression was
// confounded by carveout=100 (kills L1D) + maxblocks=4 (32-reg cap -> spills
// with 24 regs of live float4s); here: default carveout, maxblocks=3,
// 42-reg budget, no spills.
// Read: warp-per-channel LDG.128 along s, STS.32 x4 into output-layout smem
//       [sl*85+ch] (stride-85: conflict-free).
// Write: ONE cp.async.bulk (shared->global) per tile, contiguous 43,520 B.
// Sigmoid: 4-instruction approx (FMUL, MUFU.EX2, FADD, MUFU.RCP).

#define G44   44
#define GG    1936
#define CH    85
#define NA    3
#define TS    128
#define NTHR  512
#define NWARP 16

__constant__ float c_aw[NA] = {10.0f, 16.0f, 33.0f};   // scaled_anchor*STRIDE
__constant__ float c_ah[NA] = {13.0f, 30.0f, 23.0f};

__device__ __forceinline__ float sig_(float v) {
    float e;
    asm("ex2.approx.ftz.f32 %0, %1;" : "=f"(e) : "f"(v * -1.442695041f));
    float r;
    asm("rcp.approx.ftz.f32 %0, %1;" : "=f"(r) : "f"(1.0f + e));
    return r;
}

__device__ __forceinline__ float exp_(float v) {
    float e;
    asm("ex2.approx.ftz.f32 %0, %1;" : "=f"(e) : "f"(v * 1.442695041f));
    return e;
}

__global__ __launch_bounds__(NTHR, 3)
void yolo_kernel(const float* __restrict__ x, float* __restrict__ out) {
    __shared__ __align__(16) float sm[TS * CH];   // 43,520 B, output layout

    const int ba   = blockIdx.y;                  // b*NA + a (0..191)
    const int a    = ba % NA;
    const int s0   = blockIdx.x * TS;
    const int warp = threadIdx.x >> 5;
    const int lane = threadIdx.x & 31;
    const int valid = min(TS, GG - s0);           // 128, or 16 on last tile

    const int sl = lane << 2;                     // spatial offset within tile
    if (sl < valid) {
        const float* __restrict__ ib = x + (size_t)ba * (CH * GG) + (s0 + sl);
        float* __restrict__ row = sm + sl * CH;

        // ---- front-batch: 6 independent LDG.128 in flight before any math ----
        float4 v0, v1, v2, v3, v4, v5;
        v0 = *(const float4*)(ib + (size_t)(warp + 0 * NWARP) * GG);
        v1 = *(const float4*)(ib + (size_t)(warp + 1 * NWARP) * GG);
        v2 = *(const float4*)(ib + (size_t)(warp + 2 * NWARP) * GG);
        v3 = *(const float4*)(ib + (size_t)(warp + 3 * NWARP) * GG);
        v4 = *(const float4*)(ib + (size_t)(warp + 4 * NWARP) * GG);
        if (warp < 5)
            v5 = *(const float4*)(ib + (size_t)(warp + 5 * NWARP) * GG);

        // ---- ch = warp (0..15): special cases live only here ----
        {
            const int ch = warp;
            float t0, t1, t2, t3;
            if (ch >= 4) {                        // warp-uniform
                t0 = sig_(v0.x); t1 = sig_(v0.y);
                t2 = sig_(v0.z); t3 = sig_(v0.w);
            } else if (ch == 0) {
                const int s  = s0 + sl;
                const int gx = s - (s / G44) * G44;   // s%4==0, 44%4==0
                t0 = (sig_(v0.x) + (float)(gx + 0)) * 8.0f;
                t1 = (sig_(v0.y) + (float)(gx + 1)) * 8.0f;
                t2 = (sig_(v0.z) + (float)(gx + 2)) * 8.0f;
                t3 = (sig_(v0.w) + (float)(gx + 3)) * 8.0f;
            } else if (ch == 1) {
                const float fy = (float)((s0 + sl) / G44);
                t0 = (sig_(v0.x) + fy) * 8.0f;
                t1 = (sig_(v0.y) + fy) * 8.0f;
                t2 = (sig_(v0.z) + fy) * 8.0f;
                t3 = (sig_(v0.w) + fy) * 8.0f;
            } else if (ch == 2) {
                const float aw = c_aw[a];
                t0 = exp_(v0.x) * aw; t1 = exp_(v0.y) * aw;
                t2 = exp_(v0.z) * aw; t3 = exp_(v0.w) * aw;
            } else {                              // ch == 3
                const float ah = c_ah[a];
                t0 = exp_(v0.x) * ah; t1 = exp_(v0.y) * ah;
                t2 = exp_(v0.z) * ah; t3 = exp_(v0.w) * ah;
            }
            row[0 * CH + ch] = t0;
            row[1 * CH + ch] = t1;
            row[2 * CH + ch] = t2;
            row[3 * CH + ch] = t3;
        }

        // ---- remaining channels: pure sigmoid ----
        {
            const int ch = warp + 1 * NWARP;
            row[0 * CH + ch] = sig_(v1.x); row[1 * CH + ch] = sig_(v1.y);
            row[2 * CH + ch] = sig_(v1.z); row[3 * CH + ch] = sig_(v1.w);
        }
        {
            const int ch = warp + 2 * NWARP;
            row[0 * CH + ch] = sig_(v2.x); row[1 * CH + ch] = sig_(v2.y);
            row[2 * CH + ch] = sig_(v2.z); row[3 * CH + ch] = sig_(v2.w);
        }
        {
            const int ch = warp + 3 * NWARP;
            row[0 * CH + ch] = sig_(v3.x); row[1 * CH + ch] = sig_(v3.y);
            row[2 * CH + ch] = sig_(v3.z); row[3 * CH + ch] = sig_(v3.w);
        }
        {
            const int ch = warp + 4 * NWARP;
            row[0 * CH + ch] = sig_(v4.x); row[1 * CH + ch] = sig_(v4.y);
            row[2 * CH + ch] = sig_(v4.z); row[3 * CH + ch] = sig_(v4.w);
        }
        if (warp < 5) {
            const int ch = warp + 5 * NWARP;      // 80..84
            row[0 * CH + ch] = sig_(v5.x); row[1 * CH + ch] = sig_(v5.y);
            row[2 * CH + ch] = sig_(v5.z); row[3 * CH + ch] = sig_(v5.w);
        }
    }

    __syncthreads();

    // ---- write: single bulk async copy smem -> gmem (contiguous tile) ----
    if (threadIdx.x == 0) {
        uint32_t saddr;
        asm volatile("{ .reg .u64 t; cvta.to.shared.u64 t, %1; cvt.u32.u64 %0, t; }"
                     : "=r"(saddr) : "l"(sm));
        float* gptr = out + ((size_t)ba * GG + s0) * CH;   // 16B-aligned
        const uint32_t bytes = (uint32_t)(valid * CH * 4); // multiple of 16

        asm volatile("fence.proxy.async.shared::cta;" ::: "memory");
        asm volatile("cp.async.bulk.global.shared::cta.bulk_group [%0], [%1], %2;"
                     :: "l"(gptr), "r"(saddr), "r"(bytes) : "memory");
        asm volatile("cp.async.bulk.commit_group;" ::: "memory");
        asm volatile("cp.async.bulk.wait_group.read 0;" ::: "memory");
    }
}

extern "C" void kernel_launch(void* const* d_in, const int* in_sizes, int n_in,
                              void* d_out, int out_size) {
    const float* x = (const float*)d_in[0];
    float* out = (float*)d_out;

    dim3 grid((GG + TS - 1) / TS,   // 16 spatial tiles
              64 * NA);             // 192 (b,a) matrices
    yolo_kernel<<<grid, NTHR>>>(x, out);
}